// round 17
// baseline (speedup 1.0000x reference)
#include <cuda_runtime.h>
#include <cuda_fp16.h>
#include <cstdint>

#define NN 20000
#define EE 160000
#define GG 64
#define MAXD 512
#define WTOT 688128

// ---------------- scratch ----------------------------------------------------
__device__ __align__(16) unsigned short g_xh[NN * 128];
__device__ __align__(16) unsigned short g_xl[NN * 128];
__device__ __align__(16) unsigned short g_agh[NN * MAXD];
__device__ __align__(16) unsigned short g_agl[NN * MAXD];
__device__ __align__(16) unsigned short g_Ah[NN * MAXD];
__device__ __align__(16) unsigned short g_Al[NN * MAXD];
__device__ __align__(16) unsigned short g_Bh[NN * MAXD];
__device__ __align__(16) unsigned short g_Bl[NN * MAXD];
__device__ __align__(16) float          g_f32[NN * MAXD];   // f32 copy for agg/pool
__device__ __align__(16) unsigned short g_wlh[WTOT];
__device__ __align__(16) unsigned short g_wll[WTOT];
__device__ __align__(16) unsigned short g_wrh[WTOT];
__device__ __align__(16) unsigned short g_wrl[WTOT];
__device__ int   g_deg[NN];          // zero at load; k_scan re-zeroes
__device__ int   g_rowptr[NN + 1];
__device__ int   g_fill[NN];
__device__ int   g_csr[EE];
__device__ float g_pool[GG * 256];

__constant__ int c_din[6]  = {128, 256, 256, 512, 512, 256};
__constant__ int c_dout[6] = {256, 256, 512, 512, 256, 256};
__constant__ int c_woff[6] = {0, 32768, 98304, 229376, 491520, 622592};

struct WPtrs { const float* w[12]; };

// ---------------- helpers ----------------------------------------------------
__device__ __forceinline__ uint32_t smem_u32(const void* p) {
    uint32_t a;
    asm("{ .reg .u64 t; cvta.to.shared.u64 t, %1; cvt.u32.u64 %0, t; }" : "=r"(a) : "l"(p));
    return a;
}
__device__ __forceinline__ uint32_t pk2h(float a, float b) {  // low16=a, high16=b
    uint32_t r;
    asm("cvt.rn.f16x2.f32 %0, %1, %2;" : "=r"(r) : "f"(b), "f"(a));
    return r;
}
__device__ __forceinline__ void split2(float v0, float v1, uint32_t& hp, uint32_t& lp) {
    hp = pk2h(v0, v1);
    __half2 hh = *reinterpret_cast<__half2*>(&hp);
    float2 hf = __half22float2(hh);
    lp = pk2h(v0 - hf.x, v1 - hf.y);
}
__device__ __forceinline__ void ldm4(uint32_t* r, uint32_t a) {
    asm volatile("ldmatrix.sync.aligned.m8n8.x4.shared.b16 {%0,%1,%2,%3}, [%4];"
                 : "=r"(r[0]), "=r"(r[1]), "=r"(r[2]), "=r"(r[3]) : "r"(a));
}
__device__ __forceinline__ void ldm2(uint32_t* r, uint32_t a) {
    asm volatile("ldmatrix.sync.aligned.m8n8.x2.shared.b16 {%0,%1}, [%2];"
                 : "=r"(r[0]), "=r"(r[1]) : "r"(a));
}
#define MMA_F16F32(c, a, b)                                                        \
    asm volatile("mma.sync.aligned.m16n8k16.row.col.f32.f16.f16.f32 "              \
        "{%0,%1,%2,%3}, {%4,%5,%6,%7}, {%8,%9}, {%0,%1,%2,%3};"                     \
        : "+f"((c)[0]), "+f"((c)[1]), "+f"((c)[2]), "+f"((c)[3])                    \
        : "r"((a)[0]), "r"((a)[1]), "r"((a)[2]), "r"((a)[3]),                       \
          "r"((b)[0]), "r"((b)[1]))
#define CP16(dst, src, sz)                                                         \
    asm volatile("cp.async.cg.shared.global [%0], [%1], 16, %2;"                    \
        :: "r"(dst), "l"(src), "r"(sz) : "memory")
#define CP_COMMIT() asm volatile("cp.async.commit_group;" ::: "memory")
#define CP_WAIT1()  asm volatile("cp.async.wait_group 1;" ::: "memory")

// ---------------- fused convert: x split + weight transpose/split -----------
__global__ void k_cvtall(const float* __restrict__ x, WPtrs wp) {
    int t = threadIdx.x;
    if (blockIdx.y == 0) {
        int gi = blockIdx.x * 256 + t;
        if (gi < NN * 16) {
            const float4* xs = (const float4*)(x + (size_t)gi * 8);
            float4 v0 = xs[0], v1 = xs[1];
            uint32_t h0, l0, h1, l1, h2, l2, h3, l3;
            split2(v0.x, v0.y, h0, l0); split2(v0.z, v0.w, h1, l1);
            split2(v1.x, v1.y, h2, l2); split2(v1.z, v1.w, h3, l3);
            ((uint4*)g_xh)[gi] = make_uint4(h0, h1, h2, h3);
            ((uint4*)g_xl)[gi] = make_uint4(l0, l1, l2, l3);
        }
    } else {
        int id = blockIdx.y - 1, li = id >> 1, lr = id & 1;
        int K = c_din[li], Ncol = c_dout[li];
        int i = blockIdx.x * 256 + t;
        if (i < K * Ncol) {
            int k = i / Ncol, n = i % Ncol;
            float v = wp.w[id][i];
            uint32_t hp, lp;
            split2(v, 0.f, hp, lp);
            unsigned short* wh = (lr ? g_wrh : g_wlh) + c_woff[li];
            unsigned short* wl = (lr ? g_wrl : g_wll) + c_woff[li];
            wh[(size_t)n * K + k] = (unsigned short)(hp & 0xFFFFu);
            wl[(size_t)n * K + k] = (unsigned short)(lp & 0xFFFFu);
        }
    }
}

// ---------------- CSR build (parallel; scan self-zeroes g_deg) --------------
__global__ void k_count(const int* __restrict__ ei) {
    int e = blockIdx.x * blockDim.x + threadIdx.x;
    if (e < EE) atomicAdd(&g_deg[ei[EE + e]], 1);
}
__global__ void k_scan() {
    __shared__ int part[1024];
    int t = threadIdx.x;
    const int CH = (NN + 1023) / 1024;
    int base = t * CH, s = 0;
    for (int i = 0; i < CH; i++) { int idx = base + i; if (idx < NN) s += g_deg[idx]; }
    part[t] = s;
    __syncthreads();
    for (int off = 1; off < 1024; off <<= 1) {
        int v = (t >= off) ? part[t - off] : 0;
        __syncthreads(); part[t] += v; __syncthreads();
    }
    int run = (t == 0) ? 0 : part[t - 1];
    for (int i = 0; i < CH; i++) {
        int idx = base + i;
        if (idx < NN) {
            int c = g_deg[idx];
            g_rowptr[idx] = run; g_fill[idx] = run; run += c;
            g_deg[idx] = 0;
        }
    }
    if (t == 1023) g_rowptr[NN] = part[1023];
}
__global__ void k_fillcsr(const int* __restrict__ ei) {
    int e = blockIdx.x * blockDim.x + threadIdx.x;
    if (e < EE) { int d = ei[EE + e]; int p = atomicAdd(&g_fill[d], 1); g_csr[p] = ei[e]; }
}

// ---------------- mean aggregation from f32: warp=(node, 128-chunk) ---------
__global__ void k_agg(const float* __restrict__ in,
                      unsigned short* __restrict__ oh, unsigned short* __restrict__ ol, int K) {
    int node = blockIdx.x * 8 + (threadIdx.x >> 5);
    if (node >= NN) return;
    int lane = threadIdx.x & 31;
    int rs = K >> 2;                       // float4 per row
    int cidx = blockIdx.y * 32 + lane;
    int beg = g_rowptr[node], end = g_rowptr[node + 1];
    const float4* base = (const float4*)in;

    float a0[4], a1[4], a2[4], a3[4];
#pragma unroll
    for (int j = 0; j < 4; j++) { a0[j] = 0.f; a1[j] = 0.f; a2[j] = 0.f; a3[j] = 0.f; }

    int e = beg;
    for (; e + 4 <= end; e += 4) {
        int s0 = g_csr[e], s1 = g_csr[e + 1], s2 = g_csr[e + 2], s3 = g_csr[e + 3];
        float4 v0 = base[(size_t)s0 * rs + cidx];
        float4 v1 = base[(size_t)s1 * rs + cidx];
        float4 v2 = base[(size_t)s2 * rs + cidx];
        float4 v3 = base[(size_t)s3 * rs + cidx];
        a0[0] += v0.x; a0[1] += v0.y; a0[2] += v0.z; a0[3] += v0.w;
        a1[0] += v1.x; a1[1] += v1.y; a1[2] += v1.z; a1[3] += v1.w;
        a2[0] += v2.x; a2[1] += v2.y; a2[2] += v2.z; a2[3] += v2.w;
        a3[0] += v3.x; a3[1] += v3.y; a3[2] += v3.z; a3[3] += v3.w;
    }
    for (; e < end; e++) {
        float4 v = base[(size_t)g_csr[e] * rs + cidx];
        a0[0] += v.x; a0[1] += v.y; a0[2] += v.z; a0[3] += v.w;
    }

    int d = end - beg;
    float inv = 1.0f / (float)(d > 0 ? d : 1);
    float m[4];
#pragma unroll
    for (int j = 0; j < 4; j++) m[j] = ((a0[j] + a1[j]) + (a2[j] + a3[j])) * inv;
    uint32_t hp0, lp0, hp1, lp1;
    split2(m[0], m[1], hp0, lp0);
    split2(m[2], m[3], hp1, lp1);
    ((uint2*)oh)[(size_t)node * rs + cidx] = make_uint2(hp0, hp1);
    ((uint2*)ol)[(size_t)node * rs + cidx] = make_uint2(lp0, lp1);
}

// ---------------- fp16 3-term dual GEMM: 64x128 tile, 3-stage, 2 CTAs/SM ----
#define T_AH 0
#define T_AL 4096
#define T_BH 8192
#define T_BL 16384
#define STAGE_B 24576
#define SMEM_BYTES 73728

template <bool LEAKY>
__global__ void __launch_bounds__(256) k_gemm_tc(
    const unsigned short* __restrict__ a1h, const unsigned short* __restrict__ a1l,
    const unsigned short* __restrict__ a2h, const unsigned short* __restrict__ a2l,
    const unsigned short* __restrict__ b1h, const unsigned short* __restrict__ b1l,
    const unsigned short* __restrict__ b2h, const unsigned short* __restrict__ b2l,
    const float* __restrict__ bias,
    unsigned short* __restrict__ Oh, unsigned short* __restrict__ Ol,
    float* __restrict__ Of,
    int K, int DOUT)
{
    extern __shared__ char smem[];
    const uint32_t sb = smem_u32(smem);
    const int t = threadIdx.x, lane = t & 31, wid = t >> 5;
    const int wr = wid >> 2, wc = wid & 3;   // 2 x 4 warp grid, warp tile 32x32
    const int m0 = blockIdx.y * 64, n0 = blockIdx.x * 128;
    const int nc = K / 32, tot = 2 * nc;

    float acc[2][4][4];
#pragma unroll
    for (int i = 0; i < 2; i++)
#pragma unroll
        for (int j = 0; j < 4; j++)
#pragma unroll
            for (int k = 0; k < 4; k++) acc[i][j][k] = 0.f;

    // fill constants: row0 = t>>2 (0..63), granule g = t&3; 64B rows, swizzled
    const int row0 = t >> 2;
    const int g = t & 3;
    const uint32_t d0 = (uint32_t)row0 * 64 + (((uint32_t)g * 16) ^ (((uint32_t)row0 & 6) << 3));
    const uint32_t d1 = d0 + 4096;           // B rows 64..127
    const int gra = m0 + row0;
    const uint32_t szA = (gra < NN) ? 16u : 0u;
    const size_t aoff = (size_t)(gra < NN ? gra : NN - 1) * K + g * 8;
    const size_t boff0 = (size_t)(n0 + row0) * K + g * 8;
    const size_t boff1 = (size_t)(n0 + row0 + 64) * K + g * 8;

    // MMA fragment address constants
    const uint32_t fxor = ((uint32_t)(lane & 6)) << 3;
    const int ra = wr * 32 + (lane & 7) + ((lane >> 3) & 1) * 8;
    const uint32_t achk = ((uint32_t)(lane >> 4)) * 16;
    const int rb = wc * 32 + (lane & 7);
    const uint32_t bchk = ((uint32_t)((lane >> 3) & 1)) * 16;

#define FILL(ch, stg) do {                                                         \
    const unsigned short *ah_, *al_, *bh_, *bl_; int kb_;                          \
    if ((ch) < nc) { ah_ = a1h; al_ = a1l; bh_ = b1h; bl_ = b1l; kb_ = (ch) * 32; } \
    else           { ah_ = a2h; al_ = a2l; bh_ = b2h; bl_ = b2l; kb_ = ((ch) - nc) * 32; } \
    uint32_t s0_ = sb + (uint32_t)(stg) * STAGE_B;                                 \
    CP16(s0_ + T_AH + d0, ah_ + aoff + kb_, szA);                                  \
    CP16(s0_ + T_AL + d0, al_ + aoff + kb_, szA);                                  \
    CP16(s0_ + T_BH + d0, bh_ + boff0 + kb_, 16u);                                 \
    CP16(s0_ + T_BH + d1, bh_ + boff1 + kb_, 16u);                                 \
    CP16(s0_ + T_BL + d0, bl_ + boff0 + kb_, 16u);                                 \
    CP16(s0_ + T_BL + d1, bl_ + boff1 + kb_, 16u);                                 \
    CP_COMMIT();                                                                   \
} while (0)

    FILL(0, 0);
    FILL(1, 1);

    int stg = 0;
    for (int ch = 0; ch < tot; ch++) {
        CP_WAIT1();
        __syncthreads();
        if (ch + 2 < tot) {
            int ns = stg + 2; if (ns >= 3) ns -= 3;
            FILL(ch + 2, ns);
        } else {
            CP_COMMIT();
        }

        const uint32_t s0 = sb + (uint32_t)stg * STAGE_B;
#pragma unroll
        for (int ks = 0; ks < 2; ks++) {
            uint32_t ahf[2][4], alf[2][4], bhf[4][2], blf[4][2];
#pragma unroll
            for (int mt = 0; mt < 2; mt++) {
                uint32_t base = s0 + (uint32_t)(ra + mt * 16) * 64;
                ldm4(ahf[mt], base + T_AH + (((uint32_t)(ks * 32) + achk) ^ fxor));
                ldm4(alf[mt], base + T_AL + (((uint32_t)(ks * 32) + achk) ^ fxor));
            }
#pragma unroll
            for (int nt = 0; nt < 4; nt++) {
                uint32_t base = s0 + (uint32_t)(rb + nt * 8) * 64;
                ldm2(bhf[nt], base + T_BH + (((uint32_t)(ks * 32) + bchk) ^ fxor));
                ldm2(blf[nt], base + T_BL + (((uint32_t)(ks * 32) + bchk) ^ fxor));
            }
#pragma unroll
            for (int mt = 0; mt < 2; mt++)
#pragma unroll
                for (int nt = 0; nt < 4; nt++) {
                    MMA_F16F32(acc[mt][nt], ahf[mt], bhf[nt]);
                    MMA_F16F32(acc[mt][nt], ahf[mt], blf[nt]);
                    MMA_F16F32(acc[mt][nt], alf[mt], bhf[nt]);
                }
        }
        stg++; if (stg >= 3) stg = 0;
    }
#undef FILL

    // epilogue: bias; optional leaky; write hi/lo planes + f32 copy
#pragma unroll
    for (int mt = 0; mt < 2; mt++) {
        int r0 = m0 + wr * 32 + mt * 16 + (lane >> 2);
        int r1 = r0 + 8;
#pragma unroll
        for (int nt = 0; nt < 4; nt++) {
            int c0 = n0 + wc * 32 + nt * 8 + (lane & 3) * 2;
            float2 b2 = *(const float2*)(bias + c0);
            float v0 = acc[mt][nt][0] + b2.x;
            float v1 = acc[mt][nt][1] + b2.y;
            float v2 = acc[mt][nt][2] + b2.x;
            float v3 = acc[mt][nt][3] + b2.y;
            if (LEAKY) {
                v0 = v0 >= 0.f ? v0 : 0.01f * v0;
                v1 = v1 >= 0.f ? v1 : 0.01f * v1;
                v2 = v2 >= 0.f ? v2 : 0.01f * v2;
                v3 = v3 >= 0.f ? v3 : 0.01f * v3;
            }
            uint32_t hp, lp;
            if (r0 < NN) {
                size_t o = (size_t)r0 * DOUT + c0;
                split2(v0, v1, hp, lp);
                *(uint32_t*)(Oh + o) = hp;
                *(uint32_t*)(Ol + o) = lp;
                *(float2*)(Of + o) = make_float2(v0, v1);
            }
            if (r1 < NN) {
                size_t o = (size_t)r1 * DOUT + c0;
                split2(v2, v3, hp, lp);
                *(uint32_t*)(Oh + o) = hp;
                *(uint32_t*)(Ol + o) = lp;
                *(float2*)(Of + o) = make_float2(v2, v3);
            }
        }
    }
}

// ---------------- pool (binary-search bounds, f32 input) + head --------------
__global__ void k_pool(const float* __restrict__ H, const int* __restrict__ batch) {
    __shared__ int ss, ee;
    int gidx = blockIdx.x, f = threadIdx.x;
    if (f == 0) {
        int lo = 0, hi = NN;
        while (lo < hi) { int m = (lo + hi) >> 1; if (batch[m] < gidx) lo = m + 1; else hi = m; }
        ss = lo;
        hi = NN;
        while (lo < hi) { int m = (lo + hi) >> 1; if (batch[m] < gidx + 1) lo = m + 1; else hi = m; }
        ee = lo;
    }
    __syncthreads();
    int s = ss, e = ee;
    float sum = 0.f;
    for (int n = s; n < e; n++) sum += H[(size_t)n * 256 + f];
    int c = e - s; if (c < 1) c = 1;
    g_pool[gidx * 256 + f] = sum / (float)c;
}
__global__ void k_final(const float* __restrict__ Wlin, const float* __restrict__ blin,
                        float* __restrict__ out) {
    int idx = threadIdx.x;
    if (idx >= GG * 6) return;
    int g = idx / 6, o = idx % 6;
    float s = blin[o];
#pragma unroll 8
    for (int k = 0; k < 256; k++) s += g_pool[g * 256 + k] * Wlin[k * 6 + o];
    out[idx] = s;
}

// ---------------- launcher ----------------------------------------------------
extern "C" void kernel_launch(void* const* d_in, const int* in_sizes, int n_in,
                              void* d_out, int out_size) {
    const float* x     = (const float*)d_in[0];
    const int*   ei    = (const int*)d_in[1];
    const int*   batch = (const int*)d_in[2];
    WPtrs wp;
    const float* blp[6];
    for (int l = 0; l < 6; l++) {
        wp.w[2 * l]     = (const float*)d_in[3 + 3 * l];  // Wl
        blp[l]          = (const float*)d_in[4 + 3 * l];
        wp.w[2 * l + 1] = (const float*)d_in[5 + 3 * l];  // Wr
    }
    const float* Wlin = (const float*)d_in[21];
    const float* blin = (const float*)d_in[22];
    float* out = (float*)d_out;

    unsigned short *xh, *xl, *agh, *agl, *Ah, *Al, *Bh, *Bl, *wlh, *wll, *wrh, *wrl;
    float *f32;
    cudaGetSymbolAddress((void**)&xh, g_xh);   cudaGetSymbolAddress((void**)&xl, g_xl);
    cudaGetSymbolAddress((void**)&agh, g_agh); cudaGetSymbolAddress((void**)&agl, g_agl);
    cudaGetSymbolAddress((void**)&Ah, g_Ah);   cudaGetSymbolAddress((void**)&Al, g_Al);
    cudaGetSymbolAddress((void**)&Bh, g_Bh);   cudaGetSymbolAddress((void**)&Bl, g_Bl);
    cudaGetSymbolAddress((void**)&wlh, g_wlh); cudaGetSymbolAddress((void**)&wll, g_wll);
    cudaGetSymbolAddress((void**)&wrh, g_wrh); cudaGetSymbolAddress((void**)&wrl, g_wrl);
    cudaGetSymbolAddress((void**)&f32, g_f32);

    cudaFuncSetAttribute(k_gemm_tc<true>,  cudaFuncAttributeMaxDynamicSharedMemorySize, SMEM_BYTES);
    cudaFuncSetAttribute(k_gemm_tc<false>, cudaFuncAttributeMaxDynamicSharedMemorySize, SMEM_BYTES);

    const int din[6]  = {128, 256, 256, 512, 512, 256};
    const int dout[6] = {256, 256, 512, 512, 256, 256};
    const int woff[6] = {0, 32768, 98304, 229376, 491520, 622592};

    // setup
    k_cvtall<<<dim3(1250, 13), 256>>>(x, wp);
    k_count<<<(EE + 255) / 256, 256>>>(ei);
    k_scan<<<1, 1024>>>();
    k_fillcsr<<<(EE + 255) / 256, 256>>>(ei);

    const unsigned short* inh = xh; const unsigned short* inl = xl;
    const float* inf = x;  // layer 0 aggregates the raw f32 input
    for (int l = 0; l < 6; l++) {
        unsigned short* oh = (l & 1) ? Bh : Ah;
        unsigned short* ol = (l & 1) ? Bl : Al;
        dim3 agrid((NN + 7) / 8, din[l] >> 7);
        k_agg<<<agrid, 256>>>(inf, agh, agl, din[l]);
        dim3 grid(dout[l] / 128, (NN + 63) / 64);
        if (l < 5)
            k_gemm_tc<true><<<grid, 256, SMEM_BYTES>>>(
                agh, agl, inh, inl,
                wlh + woff[l], wll + woff[l], wrh + woff[l], wrl + woff[l],
                blp[l], oh, ol, f32, din[l], dout[l]);
        else
            k_gemm_tc<false><<<grid, 256, SMEM_BYTES>>>(
                agh, agl, inh, inl,
                wlh + woff[l], wll + woff[l], wrh + woff[l], wrl + woff[l],
                blp[l], oh, ol, f32, din[l], dout[l]);
        inh = oh; inl = ol; inf = f32;
    }
    k_pool<<<GG, 256>>>(f32, batch);
    k_final<<<1, 384>>>(Wlin, blin, out);
}